// round 7
// baseline (speedup 1.0000x reference)
#include <cuda_runtime.h>
#include <cuda_bf16.h>
#include <cstdint>

// Batched inverse of 3x3 upper-triangular matrices, rows of 9 fp32.
//   in : [a b c | . d e | . . f]
//   out: [1/a  -b/(ad)  (be-cd)/(adf) | 0  1/d  -e/(df) | 0 0 1/f]
//
// R7: last unfalsified limiter is DRAM read/write bus-turnaround (DRAM pinned
// at 80-82% across register-path, cp.async, and bulk-TMA kernels; LSU ruled
// out in R6). Double the per-CTA burst granularity at NO occupancy cost:
// 512 rows / 18.4KB smem / 256 threads -> still 8 CTAs/SM (147KB < 228KB),
// 64 warps, but each CTA issues 18KB same-direction bursts (2x longer runs
// per DRAM channel) and the grid halves (less CTA churn).
//
// Math: single reciprocal per row: ip = rcp(a*d*f);
//   1/a=(d*f)ip  1/d=(a*f)ip  1/f=(a*d)ip
//   o01=-(b*f)ip o12=-(e*a)ip o02=(b*e-c*d)ip
// Banks: staging = consecutive float4 (conflict-free); compute addresses
// word 9t+k and 9(t+256)+k, gcd(9,32)=1 -> conflict-free.

#define THREADS 256
#define ROWS_PER_BLOCK 512
#define FLOATS_PER_BLOCK (ROWS_PER_BLOCK * 9)   // 4608
#define VEC_PER_BLOCK (FLOATS_PER_BLOCK / 4)    // 1152  (4.5 per thread)

__device__ __forceinline__ void inv3_row(const float* __restrict__ p,
                                         float* __restrict__ q)
{
    float a = p[0], b = p[1], c = p[2];
    float d = p[4], e = p[5];
    float f = p[8];

    float ad = a * d;
    float df = d * f;
    float af = a * f;
    float ip = __frcp_rn(ad * f);      // single reciprocal: 1/(a d f)

    float ia  = df * ip;               // 1/a
    float id  = af * ip;               // 1/d
    float iff = ad * ip;               // 1/f
    float o01 = -(b * f) * ip;         // -b/(ad)
    float o12 = -(e * a) * ip;         // -e/(df)
    float o02 = (b * e - c * d) * ip;  // (be - cd)/(adf)

    q[0] = ia;
    q[1] = o01;
    q[2] = o02;
    q[3] = 0.0f;
    q[4] = id;
    q[5] = o12;
    q[6] = 0.0f;
    q[7] = 0.0f;
    q[8] = iff;
}

__global__ __launch_bounds__(THREADS, 8) void inv3_vec_kernel(
    const float4* __restrict__ in, float4* __restrict__ out)
{
    __shared__ float s[FLOATS_PER_BLOCK];  // 18432 B

    const long long base_vec = (long long)blockIdx.x * VEC_PER_BLOCK;
    float4* sv = reinterpret_cast<float4*>(s);

    // ---- Stage in: 1152 float4, 4-5 per thread, coalesced, evict-first ----
#pragma unroll
    for (int i = 0; i < 5; i++) {
        int li = threadIdx.x + i * THREADS;
        if (li < VEC_PER_BLOCK)
            sv[li] = __ldcs(&in[base_vec + li]);
    }
    __syncthreads();

    // ---- Compute: 2 rows per thread, in place in smem ----
    {
        float* p0 = &s[threadIdx.x * 9];
        inv3_row(p0, p0);
        float* p1 = &s[(threadIdx.x + THREADS) * 9];
        inv3_row(p1, p1);
    }
    __syncthreads();

    // ---- Stage out: 1152 float4, coalesced, streaming stores ----
#pragma unroll
    for (int i = 0; i < 5; i++) {
        int li = threadIdx.x + i * THREADS;
        if (li < VEC_PER_BLOCK)
            __stcs(&out[base_vec + li], sv[li]);
    }
}

// Scalar tail for rows not covered by full blocks.
__global__ void inv3_tail_kernel(const float* __restrict__ in,
                                 float* __restrict__ out, int nrows)
{
    int row = blockIdx.x * blockDim.x + threadIdx.x;
    if (row >= nrows) return;
    inv3_row(in + (long long)row * 9, out + (long long)row * 9);
}

extern "C" void kernel_launch(void* const* d_in, const int* in_sizes, int n_in,
                              void* d_out, int out_size)
{
    const float* x = (const float*)d_in[0];
    float* y = (float*)d_out;
    long long total_floats = in_sizes[0];
    long long nrows = total_floats / 9;

    long long nblocks = nrows / ROWS_PER_BLOCK;
    if (nblocks > 0) {
        inv3_vec_kernel<<<(unsigned)nblocks, THREADS>>>(
            (const float4*)x, (float4*)y);
    }
    long long done = nblocks * ROWS_PER_BLOCK;
    int rem = (int)(nrows - done);
    if (rem > 0) {
        inv3_tail_kernel<<<(rem + 255) / 256, 256>>>(
            x + done * 9, y + done * 9, rem);
    }
}

// round 8
// speedup vs baseline: 1.0092x; 1.0092x over previous
#include <cuda_runtime.h>
#include <cuda_bf16.h>
#include <cstdint>

// Batched inverse of 3x3 upper-triangular matrices, rows of 9 fp32.
//   in : [a b c | . d e | . . f]
//   out: [1/a  -b/(ad)  (be-cd)/(adf) | 0  1/d  -e/(df) | 0 0 1/f]
//
// R8: warp-autonomous variant. All prior kernels convoy 8 warps through
// block-wide barriers (load->bar->compute->bar->store); the last-arriving
// line stalls all 8 warps. Here each warp owns a private 64-row / 2304B
// smem slice and syncs only with __syncwarp(): warps drift apart and their
// memory phases self-interleave, removing convoy bubbles at zero occupancy
// cost (18KB/CTA -> 8 CTAs/SM, 64 warps resident).
//
// Alignment: warp slice = 2304B = 18x128B, so per-warp global chunks are
// 128B-aligned and all LDG.128/STG.128 fully coalesced.
// Banks: warp smem base = w*576 floats (576 % 32 == 0); compute addresses
// 9*lane + k, gcd(9,32)=1 -> conflict-free within each warp.
// Math: single reciprocal per row: ip = rcp(a*d*f).

#define THREADS 256
#define WARPS 8
#define ROWS_PER_WARP 64
#define ROWS_PER_BLOCK (WARPS * ROWS_PER_WARP)          // 512
#define FLOATS_PER_WARP (ROWS_PER_WARP * 9)             // 576
#define VECS_PER_WARP (FLOATS_PER_WARP / 4)             // 144
#define FLOATS_PER_BLOCK (ROWS_PER_BLOCK * 9)           // 4608

__device__ __forceinline__ void inv3_row(const float* __restrict__ p,
                                         float* __restrict__ q)
{
    float a = p[0], b = p[1], c = p[2];
    float d = p[4], e = p[5];
    float f = p[8];

    float ad = a * d;
    float df = d * f;
    float af = a * f;
    float ip = __frcp_rn(ad * f);      // single reciprocal: 1/(a d f)

    float ia  = df * ip;               // 1/a
    float id  = af * ip;               // 1/d
    float iff = ad * ip;               // 1/f
    float o01 = -(b * f) * ip;         // -b/(ad)
    float o12 = -(e * a) * ip;         // -e/(df)
    float o02 = (b * e - c * d) * ip;  // (be - cd)/(adf)

    q[0] = ia;
    q[1] = o01;
    q[2] = o02;
    q[3] = 0.0f;
    q[4] = id;
    q[5] = o12;
    q[6] = 0.0f;
    q[7] = 0.0f;
    q[8] = iff;
}

__global__ __launch_bounds__(THREADS, 8) void inv3_warp_kernel(
    const float4* __restrict__ in, float4* __restrict__ out)
{
    __shared__ float s[FLOATS_PER_BLOCK];  // 18432 B

    const int w    = threadIdx.x >> 5;
    const int lane = threadIdx.x & 31;

    // This warp's private slice.
    float*  ws  = &s[w * FLOATS_PER_WARP];
    float4* wsv = reinterpret_cast<float4*>(ws);
    const long long warp_vec_base =
        (long long)blockIdx.x * (FLOATS_PER_BLOCK / 4) + w * VECS_PER_WARP;

    // ---- Stage in: 144 float4 per warp (4.5/lane), coalesced, evict-first ----
#pragma unroll
    for (int j = 0; j < 5; j++) {
        int li = lane + j * 32;
        if (li < VECS_PER_WARP)
            wsv[li] = __ldcs(&in[warp_vec_base + li]);
    }
    __syncwarp();

    // ---- Compute: 2 rows per lane, in place in the warp slice ----
    {
        float* p0 = &ws[lane * 9];
        inv3_row(p0, p0);
        float* p1 = &ws[(lane + 32) * 9];
        inv3_row(p1, p1);
    }
    __syncwarp();

    // ---- Stage out: 144 float4 per warp, coalesced, streaming ----
#pragma unroll
    for (int j = 0; j < 5; j++) {
        int li = lane + j * 32;
        if (li < VECS_PER_WARP)
            __stcs(&out[warp_vec_base + li], wsv[li]);
    }
}

// Scalar tail for rows not covered by full blocks (not hit for N=8388608).
__global__ void inv3_tail_kernel(const float* __restrict__ in,
                                 float* __restrict__ out, int nrows)
{
    int row = blockIdx.x * blockDim.x + threadIdx.x;
    if (row >= nrows) return;
    inv3_row(in + (long long)row * 9, out + (long long)row * 9);
}

extern "C" void kernel_launch(void* const* d_in, const int* in_sizes, int n_in,
                              void* d_out, int out_size)
{
    const float* x = (const float*)d_in[0];
    float* y = (float*)d_out;
    long long total_floats = in_sizes[0];
    long long nrows = total_floats / 9;

    long long nblocks = nrows / ROWS_PER_BLOCK;
    if (nblocks > 0) {
        inv3_warp_kernel<<<(unsigned)nblocks, THREADS>>>(
            (const float4*)x, (float4*)y);
    }
    long long done = nblocks * ROWS_PER_BLOCK;
    int rem = (int)(nrows - done);
    if (rem > 0) {
        inv3_tail_kernel<<<(rem + 255) / 256, 256>>>(
            x + done * 9, y + done * 9, rem);
    }
}

// round 9
// speedup vs baseline: 1.0103x; 1.0011x over previous
#include <cuda_runtime.h>
#include <cuda_bf16.h>
#include <cstdint>

// Batched inverse of 3x3 upper-triangular matrices, rows of 9 fp32. FINAL.
//   in : [a b c | . d e | . . f]
//   out: [1/a  -b/(ad)  (be-cd)/(adf) | 0  1/d  -e/(df) | 0 0 1/f]
//
// Verdict after 8 rounds: HBM-stream-bound at the practical ceiling.
// 604 MB moved in 84.5us = 7.15 TB/s effective (~89% of 8 TB/s spec).
// Six independent designs (register-staged / cp.async pipeline / bulk-TMA /
// 2x bursts / warp-autonomous / streaming hints) all land within 4%;
// occupancy, MUFU, LSU/L1tex, R/W turnaround, and barrier convoys were each
// individually ruled out. This is the empirical best (R5).
//
// Shape: 256 rows / 256 threads / 9KB smem -> 8 CTAs/SM, 64 warps.
// All global traffic LDG.128/STG.128 block-contiguous with evict-first
// hints. Smem: staging = consecutive float4 (conflict-free); compute
// addresses word 9t+k, gcd(9,32)=1 -> all 32 lanes distinct banks.
// Math: ONE reciprocal per row: ip = rcp(a*d*f), everything else FMA-pipe:
//   1/a=(d*f)ip  1/d=(a*f)ip  1/f=(a*d)ip
//   o01=-(b*f)ip o12=-(e*a)ip o02=(b*e-c*d)ip
// Diagonal in [0.5,1.5) -> a*d*f in [0.125,3.4): no range issues; rel_err 7e-8.

#define THREADS 256
#define ROWS_PER_BLOCK 256
#define FLOATS_PER_BLOCK (ROWS_PER_BLOCK * 9)   // 2304
#define VEC_PER_BLOCK (FLOATS_PER_BLOCK / 4)    // 576

__device__ __forceinline__ void inv3_row(const float* __restrict__ p,
                                         float* __restrict__ q)
{
    float a = p[0], b = p[1], c = p[2];
    float d = p[4], e = p[5];
    float f = p[8];

    float ad = a * d;
    float df = d * f;
    float af = a * f;
    float ip = __frcp_rn(ad * f);      // single reciprocal: 1/(a d f)

    float ia  = df * ip;               // 1/a
    float id  = af * ip;               // 1/d
    float iff = ad * ip;               // 1/f
    float o01 = -(b * f) * ip;         // -b/(ad)
    float o12 = -(e * a) * ip;         // -e/(df)
    float o02 = (b * e - c * d) * ip;  // (be - cd)/(adf)

    q[0] = ia;
    q[1] = o01;
    q[2] = o02;
    q[3] = 0.0f;
    q[4] = id;
    q[5] = o12;
    q[6] = 0.0f;
    q[7] = 0.0f;
    q[8] = iff;
}

__global__ __launch_bounds__(THREADS, 8) void inv3_vec_kernel(
    const float4* __restrict__ in, float4* __restrict__ out)
{
    __shared__ float s[FLOATS_PER_BLOCK];  // 9216 B

    const long long base_vec = (long long)blockIdx.x * VEC_PER_BLOCK;
    float4* sv = reinterpret_cast<float4*>(s);

    // ---- Stage in: 576 float4, coalesced, evict-first ----
#pragma unroll
    for (int i = 0; i < 3; i++) {
        int li = threadIdx.x + i * THREADS;
        if (li < VEC_PER_BLOCK)
            sv[li] = __ldcs(&in[base_vec + li]);
    }
    __syncthreads();

    // ---- Compute: 1 row per thread, in place in smem ----
    {
        float* p = &s[threadIdx.x * 9];
        inv3_row(p, p);
    }
    __syncthreads();

    // ---- Stage out: 576 float4, coalesced, streaming stores ----
#pragma unroll
    for (int i = 0; i < 3; i++) {
        int li = threadIdx.x + i * THREADS;
        if (li < VEC_PER_BLOCK)
            __stcs(&out[base_vec + li], sv[li]);
    }
}

// Scalar tail for rows not covered by full blocks (not hit for N=8388608).
__global__ void inv3_tail_kernel(const float* __restrict__ in,
                                 float* __restrict__ out, int nrows)
{
    int row = blockIdx.x * blockDim.x + threadIdx.x;
    if (row >= nrows) return;
    inv3_row(in + (long long)row * 9, out + (long long)row * 9);
}

extern "C" void kernel_launch(void* const* d_in, const int* in_sizes, int n_in,
                              void* d_out, int out_size)
{
    const float* x = (const float*)d_in[0];
    float* y = (float*)d_out;
    long long total_floats = in_sizes[0];
    long long nrows = total_floats / 9;

    long long nblocks = nrows / ROWS_PER_BLOCK;
    if (nblocks > 0) {
        inv3_vec_kernel<<<(unsigned)nblocks, THREADS>>>(
            (const float4*)x, (float4*)y);
    }
    long long done = nblocks * ROWS_PER_BLOCK;
    int rem = (int)(nrows - done);
    if (rem > 0) {
        inv3_tail_kernel<<<(rem + 255) / 256, 256>>>(
            x + done * 9, y + done * 9, rem);
    }
}